// round 5
// baseline (speedup 1.0000x reference)
#include <cuda_runtime.h>
#include <cuda_fp16.h>

#define BB 2
#define NQv 1024
#define NKv 1024
#define DD 512
#define HH 32

// Scratch (no cudaMalloc allowed). 16B-aligned for vector loads.
// g_hk2[pair][h] = half2(hk[2p][h]+b1[h], hk[2p+1][h]+b1[h])  -- k-pairs
// g_hq2[row][h]  = half2(hq[row][h], hq[row][h])              -- duplicated
__device__ __align__(16) __half2 g_hk2[(BB * NKv / 2) * HH];
__device__ __align__(16) __half2 g_hq2[(BB * NQv) * HH];

__device__ __forceinline__ unsigned tanh2u(unsigned x) {
    unsigned y;
    asm("tanh.approx.f16x2 %0, %1;" : "=r"(y) : "r"(x));
    return y;
}

// ---------------------------------------------------------------------------
// Projection v5: C[2048,32] = A[2048,512] @ W[512,32] per tensor.
// 256 blocks (128 x 2 tensors) of 256 thr; block owns 16 rows; K chunked
// by 128. A chunk 8KB + W chunk 16KB in smem. Thread = 2 rows x 1 h.
// ~2x occupancy vs v4 -> latency-hiding to reach the ~4-5us FMA floor.
// ---------------------------------------------------------------------------
__global__ __launch_bounds__(256) void proj_kernel(
    const float* __restrict__ keys, const float* __restrict__ queries,
    const float* __restrict__ W1, const float* __restrict__ b1)
{
    __shared__ float as[16][128];   // A chunk: 16 rows x 128 d  (8 KB)
    __shared__ float ws[128][32];   // W chunk: 128 d x 32 h     (16 KB)

    const int z    = blockIdx.y;
    const int tid  = threadIdx.x;
    const int h    = tid & 31;
    const int warp = tid >> 5;
    const int row0 = blockIdx.x * 16;
    const float* __restrict__ src = z ? queries : keys;

    float acc0 = 0.f, acc1 = 0.f;

    for (int c = 0; c < 4; ++c) {
        // Stage A chunk: 16 rows x 32 float4 = 512 float4, 2/thread.
        {
            const float4* __restrict__ ag =
                (const float4*)(src + (size_t)row0 * DD + c * 128);
            float4* av = (float4*)&as[0][0];
            #pragma unroll
            for (int i = 0; i < 2; ++i) {
                const int idx = tid + i * 256;
                const int r = idx >> 5, j = idx & 31;
                av[idx] = __ldg(&ag[(size_t)r * (DD / 4) + j]);
            }
        }
        // Stage W chunk: 128 d x 32 h = 1024 float4, 4/thread.
        {
            const float4* __restrict__ wg =
                (const float4*)(W1 + (size_t)(z * DD + c * 128) * HH);
            float4* wv = (float4*)&ws[0][0];
            #pragma unroll
            for (int i = 0; i < 4; ++i)
                wv[tid + i * 256] = __ldg(&wg[tid + i * 256]);
        }
        __syncthreads();

        #pragma unroll 8
        for (int d4 = 0; d4 < 32; ++d4) {
            const float4 a0 = *(const float4*)&as[2 * warp + 0][d4 * 4];
            const float4 a1 = *(const float4*)&as[2 * warp + 1][d4 * 4];
            const float w0  = ws[d4 * 4 + 0][h];
            const float w1v = ws[d4 * 4 + 1][h];
            const float w2v = ws[d4 * 4 + 2][h];
            const float w3v = ws[d4 * 4 + 3][h];
            acc0 = fmaf(a0.x, w0, acc0);  acc1 = fmaf(a1.x, w0, acc1);
            acc0 = fmaf(a0.y, w1v, acc0); acc1 = fmaf(a1.y, w1v, acc1);
            acc0 = fmaf(a0.z, w2v, acc0); acc1 = fmaf(a1.z, w2v, acc1);
            acc0 = fmaf(a0.w, w3v, acc0); acc1 = fmaf(a1.w, w3v, acc1);
        }
        __syncthreads();
    }

    const int r0 = row0 + 2 * warp;
    if (z == 0) {
        const float bias = __ldg(&b1[h]);
        g_hk2[(size_t)(r0 >> 1) * HH + h] =
            __floats2half2_rn(acc0 + bias, acc1 + bias);
    } else {
        g_hq2[(size_t)(r0 + 0) * HH + h] = __float2half2_rn(acc0);
        g_hq2[(size_t)(r0 + 1) * HH + h] = __float2half2_rn(acc1);
    }
}

// ---------------------------------------------------------------------------
// Scoring v5: 64q x 64k tile per 256-thread block (512 blocks total -> one
// wave, no tail). Thread owns 4q x 2 k-pairs = 16 scores (8 half2 lanes).
// fp16 HFMA2 accumulation flushed to f32 every 8 h-steps.
// ---------------------------------------------------------------------------
__global__ __launch_bounds__(256) void score_kernel(
    const float* __restrict__ W2, const float* __restrict__ b2,
    float* __restrict__ out)
{
    __shared__ __half2 hqs2[64][33];   // (v,v) duplicated, padded
    __shared__ __half2 hks2[32][33];   // (bk0,bk1) k-pairs, padded
    __shared__ __half2 w2s2[32];       // (w,w)

    const int b   = blockIdx.z;
    const int q0  = blockIdx.y * 64;
    const int k0  = blockIdx.x * 64;
    const int tid = threadIdx.x;

    {
        const __half2* __restrict__ hq_g = g_hq2 + (size_t)(b * NQv + q0) * HH;
        #pragma unroll
        for (int it = 0; it < 8; ++it) {
            const int i = tid + it * 256;
            hqs2[i >> 5][i & 31] = hq_g[i];
        }
        const __half2* __restrict__ hk_g =
            g_hk2 + (size_t)((b * NKv + k0) >> 1) * HH;
        #pragma unroll
        for (int it = 0; it < 4; ++it) {
            const int i = tid + it * 256;
            hks2[i >> 5][i & 31] = hk_g[i];
        }
        if (tid < 32) w2s2[tid] = __float2half2_rn(__ldg(&W2[tid]));
    }
    __syncthreads();

    const int kp = tid & 15;           // k-pair A; pair B = kp+16
    const int qq = (tid >> 4) * 4;     // q base within tile

    // Master f32 accumulators: [q 0..3][pairA.lo, pairA.hi, pairB.lo, pairB.hi]
    float m[4][4];
    #pragma unroll
    for (int i = 0; i < 4; ++i)
        #pragma unroll
        for (int j = 0; j < 4; ++j) m[i][j] = 0.f;

    #pragma unroll
    for (int hb = 0; hb < 4; ++hb) {
        __half2 cA[4], cB[4];
        #pragma unroll
        for (int i = 0; i < 4; ++i) {
            cA[i] = __float2half2_rn(0.f);
            cB[i] = __float2half2_rn(0.f);
        }
        #pragma unroll
        for (int hi = 0; hi < 8; ++hi) {
            const int h = hb * 8 + hi;
            const __half2 w2h = w2s2[h];
            const __half2 bkA = hks2[kp][h];
            const __half2 bkB = hks2[kp + 16][h];
            #pragma unroll
            for (int i = 0; i < 4; ++i) {
                const __half2 qv = hqs2[qq + i][h];
                const __half2 xA = __hadd2(qv, bkA);
                const __half2 xB = __hadd2(qv, bkB);
                __half2 tA, tB;
                *(unsigned*)&tA = tanh2u(*(const unsigned*)&xA);
                *(unsigned*)&tB = tanh2u(*(const unsigned*)&xB);
                cA[i] = __hfma2(w2h, tA, cA[i]);
                cB[i] = __hfma2(w2h, tB, cB[i]);
            }
        }
        #pragma unroll
        for (int i = 0; i < 4; ++i) {
            m[i][0] += __low2float(cA[i]); m[i][1] += __high2float(cA[i]);
            m[i][2] += __low2float(cB[i]); m[i][3] += __high2float(cB[i]);
        }
    }

    const float bias = __ldg(b2);
    #pragma unroll
    for (int i = 0; i < 4; ++i) {
        float* __restrict__ o =
            out + (size_t)(b * NQv + q0 + qq + i) * NKv + k0;
        *(float2*)(o + 2 * kp) =
            make_float2(m[i][0] + bias, m[i][1] + bias);
        *(float2*)(o + 2 * kp + 32) =
            make_float2(m[i][2] + bias, m[i][3] + bias);
    }
}

extern "C" void kernel_launch(void* const* d_in, const int* in_sizes, int n_in,
                              void* d_out, int out_size)
{
    const float* keys    = (const float*)d_in[0];
    const float* queries = (const float*)d_in[1];
    const float* W1      = (const float*)d_in[2];
    const float* b1      = (const float*)d_in[3];
    const float* W2      = (const float*)d_in[4];
    const float* b2      = (const float*)d_in[5];
    float* out = (float*)d_out;

    proj_kernel<<<dim3(128, 2, 1), 256>>>(keys, queries, W1, b1);
    score_kernel<<<dim3(NKv / 64, NQv / 64, BB), 256>>>(W2, b2, out);
}